// round 15
// baseline (speedup 1.0000x reference)
#include <cuda_runtime.h>
#include <cuda_fp16.h>
#include <math.h>

// Problem constants (fixed by setup_inputs)
#define BB   2
#define LL   1024
#define KNN  50
#define HID  768
#define PE   384
#define HPE  192
#define TABN 1024

#define N_LAYOUT (BB*LL*HID)
#define N_P      (BB*LL*KNN*HID)
#define N_TOPK   (BB*LL*KNN)
#define OFF_P    (N_LAYOUT)
#define OFF_TOPK (N_LAYOUT + N_P)
#define OFF_MASK (OFF_TOPK + N_TOPK)

#define BP   196                         // B smem word pitch (half2 units)
#define SMEM_TB (64 * BP * 4 + 64 * 4)   // B tile + bias = 50432 B

typedef unsigned long long ull;

// Scratch (no dynamic allocation allowed)
__device__ __half g_sinh[TABN * PE];          // 0.75 MB sinusoidal table (fp16)
__device__ uint4  g_Th[4 * TABN * HID / 8];   // 6.3 MB fused lookup tables (fp16)
__device__ int    g_topk[BB * LL * KNN];      // topk indices for k_p / k_mask
__device__ float  g_cx[BB * LL], g_cy[BB * LL];

// ---------------------------------------------------------------------------
// Kernel 1: sinusoidal table (numpy f32 rounding of freq/angle), fp16 out
// ---------------------------------------------------------------------------
__global__ void k_sin() {
    int idx = blockIdx.x * blockDim.x + threadIdx.x;
    if (idx >= TABN * HPE) return;
    int m = idx / HPE;
    int j = idx - m * HPE;
    if (m == 0) {
        g_sinh[j] = __float2half(0.f);
        g_sinh[HPE + j] = __float2half(0.f);
        return;
    }
    const float c = (float)(-9.210340371976184 / 191.0);   // -ln(10000)/(half-1)
    float freq = expf((float)j * c);
    float ang  = (float)m * freq;                           // exact f32 angle
    g_sinh[m * PE + j]       = __float2half(sinf(ang));
    g_sinh[m * PE + HPE + j] = __float2half(cosf(ang));
}

// ---------------------------------------------------------------------------
// Kernel 2: fused tables T_t = sin_tab @ A_t^T via HMMA (mma.sync m16n8k16,
// fp16 in, f32 accum). Block = 128(M) x 64(N) tile, 8 warps, 24 K-steps.
// ---------------------------------------------------------------------------
__device__ __forceinline__ void mma16816(float* d,
        unsigned a0, unsigned a1, unsigned a2, unsigned a3,
        unsigned b0, unsigned b1) {
    asm volatile(
        "mma.sync.aligned.m16n8k16.row.col.f32.f16.f16.f32 "
        "{%0,%1,%2,%3}, {%4,%5,%6,%7}, {%8,%9}, {%0,%1,%2,%3};"
        : "+f"(d[0]), "+f"(d[1]), "+f"(d[2]), "+f"(d[3])
        : "r"(a0), "r"(a1), "r"(a2), "r"(a3), "r"(b0), "r"(b1));
}

__global__ void __launch_bounds__(256) k_tables(
        const float* __restrict__ Wtl, const float* __restrict__ Wtr,
        const float* __restrict__ Wbl, const float* __restrict__ Wbr,
        const float* __restrict__ btl, const float* __restrict__ btr,
        const float* __restrict__ bbl, const float* __restrict__ bbr) {
    int t = blockIdx.z;
    const float *WA, *WBp; int off;
    if      (t == 0) { WA = Wtl; WBp = Wbl; off = 0;  }
    else if (t == 1) { WA = Wtr; WBp = Wbr; off = 0;  }
    else if (t == 2) { WA = Wtl; WBp = Wtr; off = PE; }
    else             { WA = Wbl; WBp = Wbr; off = PE; }

    extern __shared__ unsigned sh[];
    unsigned* Bs = sh;                         // [64][BP] half2 words
    float* bias = (float*)(sh + 64 * BP);      // [64]

    int n0 = blockIdx.x * 64;
    int m0 = blockIdx.y * 128;

    for (int idx = threadIdx.x; idx < 64 * 192; idx += 256) {
        int r = idx / 192, wc = idx - r * 192;
        const float* wp = WA + (size_t)(n0 + r) * HID + off + wc * 2;
        const float* vp = WBp + (size_t)(n0 + r) * HID + off + wc * 2;
        float2 w = *(const float2*)wp;
        float2 v = *(const float2*)vp;
        __half2 h = __floats2half2_rn(w.x + v.x, w.y + v.y);
        Bs[r * BP + wc] = *(unsigned*)&h;
    }
    if (t == 0 && threadIdx.x < 64) {
        int o = n0 + threadIdx.x;
        bias[threadIdx.x] = btl[o] + btr[o] + bbl[o] + bbr[o];
    }
    __syncthreads();

    int w = threadIdx.x >> 5;
    int lane = threadIdx.x & 31;
    int g = lane >> 2;
    int q = lane & 3;
    int mrow = m0 + w * 16 + g;

    float d[8][4];
#pragma unroll
    for (int nt = 0; nt < 8; nt++)
#pragma unroll
        for (int i = 0; i < 4; i++) d[nt][i] = 0.f;

    const __half* A = g_sinh;
    for (int k0 = 0; k0 < PE; k0 += 16) {
        unsigned a0 = *(const unsigned*)&A[(size_t)mrow * PE + k0 + 2 * q];
        unsigned a1 = *(const unsigned*)&A[(size_t)(mrow + 8) * PE + k0 + 2 * q];
        unsigned a2 = *(const unsigned*)&A[(size_t)mrow * PE + k0 + 2 * q + 8];
        unsigned a3 = *(const unsigned*)&A[(size_t)(mrow + 8) * PE + k0 + 2 * q + 8];
        int kw = (k0 >> 1) + q;
#pragma unroll
        for (int nt = 0; nt < 8; nt++) {
            unsigned b0 = Bs[(nt * 8 + g) * BP + kw];
            unsigned b1 = Bs[(nt * 8 + g) * BP + kw + 4];
            mma16816(d[nt], a0, a1, a2, a3, b0, b1);
        }
    }

    __half* Tp = (__half*)g_Th;
#pragma unroll
    for (int nt = 0; nt < 8; nt++) {
        int c = nt * 8 + 2 * q;
        float b0v = 0.f, b1v = 0.f;
        if (t == 0) { b0v = bias[c]; b1v = bias[c + 1]; }
        __half2 h0 = __floats2half2_rn(d[nt][0] + b0v, d[nt][1] + b1v);
        __half2 h1 = __floats2half2_rn(d[nt][2] + b0v, d[nt][3] + b1v);
        size_t base = ((size_t)(t * TABN) + mrow) * HID + n0 + c;
        *(unsigned*)&Tp[base] = *(unsigned*)&h0;
        *(unsigned*)&Tp[base + (size_t)8 * HID] = *(unsigned*)&h1;
    }
}

// ---------------------------------------------------------------------------
// Kernel 3: layout_emb gathers + LayerNorm
// ---------------------------------------------------------------------------
__device__ __forceinline__ float block_sum_256(float v, volatile float* red) {
#pragma unroll
    for (int o = 16; o > 0; o >>= 1) v += __shfl_down_sync(0xffffffffu, v, o);
    if ((threadIdx.x & 31) == 0) red[threadIdx.x >> 5] = v;
    __syncthreads();
    if (threadIdx.x < 32) {
        float t = (threadIdx.x < 8) ? red[threadIdx.x] : 0.f;
#pragma unroll
        for (int o = 16; o > 0; o >>= 1) t += __shfl_down_sync(0xffffffffu, t, o);
        if (threadIdx.x == 0) red[8] = t;
    }
    __syncthreads();
    return red[8];
}

__global__ void k_layout(const int* __restrict__ bbox,
                         const float* __restrict__ xt, const float* __restrict__ yt,
                         const float* __restrict__ ht, const float* __restrict__ wt,
                         const float* __restrict__ g,  const float* __restrict__ be,
                         float* __restrict__ out) {
    int row = blockIdx.x;
    int4 bb = ((const int4*)bbox)[row];
    int t = threadIdx.x;

    float v[3]; int cs[3];
#pragma unroll
    for (int s = 0; s < 3; s++) {
        int c = t + s * 256; cs[s] = c;
        int seg = c >> 7, o = c & 127;
        const float* tab; int idx;
        switch (seg) {
            case 0: tab = xt; idx = bb.x; break;
            case 1: tab = yt; idx = bb.y; break;
            case 2: tab = xt; idx = bb.z; break;
            case 3: tab = yt; idx = bb.w; break;
            case 4: tab = ht; idx = bb.w - bb.y; break;
            default: tab = wt; idx = bb.z - bb.x; break;
        }
        v[s] = tab[idx * 128 + o];
    }

    __shared__ float red[9];
    float mu = block_sum_256(v[0] + v[1] + v[2], red) * (1.f / 768.f);
    float d0 = v[0] - mu, d1 = v[1] - mu, d2 = v[2] - mu;
    float var = block_sum_256(d0 * d0 + d1 * d1 + d2 * d2, red) * (1.f / 768.f);
    float inv = rsqrtf(var + 1e-12f);

    float* dst = out + (size_t)row * HID;
    dst[cs[0]] = d0 * inv * g[cs[0]] + be[cs[0]];
    dst[cs[1]] = d1 * inv * g[cs[1]] + be[cs[1]];
    dst[cs[2]] = d2 * inv * g[cs[2]] + be[cs[2]];
}

// ---------------------------------------------------------------------------
// Kernel 3b: box centers (masked -> huge coordinate)
// ---------------------------------------------------------------------------
__global__ void k_centers(const int* __restrict__ bbox, const int* __restrict__ amask) {
    int j = blockIdx.x * 256 + threadIdx.x;
    if (j >= BB * LL) return;
    int4 bv = ((const int4*)bbox)[j];
    float x1, y1, x2, y2;
    if (amask[j] == 0) { x1 = y1 = x2 = y2 = 1.0e8f; }
    else { x1 = (float)bv.x; y1 = (float)bv.y; x2 = (float)bv.z; y2 = (float)bv.w; }
    g_cx[j] = __fmul_rn(__fadd_rn(x1, x2), 0.5f);
    g_cy[j] = __fmul_rn(__fadd_rn(y1, y2), 0.5f);
}

// ---------------------------------------------------------------------------
// Kernel 4: KNN top-50 SELECT ONLY (512 threads; radix-select + tiny bitonic).
// Writes g_topk + the topk float output; mask is built later by k_mask,
// off the k_p critical path.
// ---------------------------------------------------------------------------
__global__ void __launch_bounds__(512) k_knn(float* __restrict__ out_topk) {
    __shared__ unsigned u[LL];
    __shared__ ull cand[LL];
    __shared__ int hist[256];
    __shared__ int s_bin, s_wt, s_cnt;

    int row = blockIdx.x;
    int b = row >> 10;
    int tid = threadIdx.x;

    float cx = g_cx[row], cy = g_cy[row];
    const float* bx = g_cx + b * LL;
    const float* by = g_cy + b * LL;
    for (int j = tid; j < LL; j += 512) {
        float dx = __fadd_rn(cx, -bx[j]);
        float dy = __fadd_rn(cy, -by[j]);
        float d  = __fadd_rn(__fmul_rn(dx, dx), __fmul_rn(dy, dy));
        u[j] = __float_as_uint(d);
    }
    __syncthreads();

    unsigned prefix = 0;
    int want = KNN;
    for (int pass = 0; pass < 4; pass++) {
        int shift = 24 - 8 * pass;
        if (tid < 256) hist[tid] = 0;
        __syncthreads();
        for (int j = tid; j < LL; j += 512) {
            unsigned key = u[j];
            bool ok = (pass == 0) || ((key >> (shift + 8)) == prefix);
            if (ok) atomicAdd(&hist[(key >> shift) & 255], 1);
        }
        __syncthreads();
        if (tid < 32) {
            int h[8], s = 0;
#pragma unroll
            for (int k = 0; k < 8; k++) { h[k] = hist[tid * 8 + k]; s += h[k]; }
            int inc = s;
#pragma unroll
            for (int o = 1; o < 32; o <<= 1) {
                int v = __shfl_up_sync(0xffffffffu, inc, o);
                if (tid >= o) inc += v;
            }
            int c = inc - s;
#pragma unroll
            for (int k = 0; k < 8; k++) {
                if (want > c && want <= c + h[k]) { s_bin = tid * 8 + k; s_wt = want - c; }
                c += h[k];
            }
        }
        __syncthreads();
        prefix = (prefix << 8) | (unsigned)s_bin;
        want = s_wt;
        __syncthreads();
    }
    unsigned T = prefix;

    if (tid == 0) s_cnt = 0;
    __syncthreads();
    for (int j = tid; j < LL; j += 512) {
        if (u[j] <= T) {
            int p = atomicAdd(&s_cnt, 1);
            cand[p] = ((ull)u[j] << 32) | (unsigned)j;
        }
    }
    __syncthreads();
    int cnt = s_cnt;
    int n = 64; while (n < cnt) n <<= 1;
    for (int j = cnt + tid; j < n; j += 512) cand[j] = ~0ULL;

    for (unsigned k2 = 2; k2 <= (unsigned)n; k2 <<= 1) {
        for (unsigned jj = k2 >> 1; jj > 0; jj >>= 1) {
            __syncthreads();
            for (unsigned idx = tid; idx < (unsigned)n; idx += 512) {
                unsigned ixj = idx ^ jj;
                if (ixj > idx) {
                    ull a = cand[idx], c2 = cand[ixj];
                    bool asc = ((idx & k2) == 0);
                    if ((a > c2) == asc) { cand[idx] = c2; cand[ixj] = a; }
                }
            }
        }
    }
    __syncthreads();

    if (tid < KNN) {
        int idxk = (int)(cand[tid] & 0xffffffffu);
        g_topk[row * KNN + tid] = idxk;
        out_topk[row * KNN + tid] = (float)idxk;
    }
}

// ---------------------------------------------------------------------------
// Kernel 4b: local_mask from g_topk (off the k_p critical path)
// ---------------------------------------------------------------------------
__global__ void __launch_bounds__(256) k_mask(float* __restrict__ out_mask) {
    __shared__ unsigned char flg[LL];
    int row = blockIdx.x;
    int tid = threadIdx.x;
    for (int j = tid; j < LL; j += 256) flg[j] = 0;
    __syncthreads();
    if (tid < KNN) flg[g_topk[row * KNN + tid]] = 1;
    __syncthreads();
    float* mrow = out_mask + (size_t)row * LL;
    for (int j = tid; j < LL; j += 256) __stcs(&mrow[j], (float)flg[j]);
}

// ---------------------------------------------------------------------------
// Kernel 5: p = T0[m1] + T1[m2] + T2[m3] + T3[m4]  (fp16 tables, f32 out)
// R12/R13 winner: lane0+shfl indices; uint2 loads, coalesced float4 stores.
// ---------------------------------------------------------------------------
__device__ __forceinline__ int midx(int d) {
    d = d < -1000 ? -1000 : (d > 1000 ? 1000 : d);
    return d & 1023;
}
__device__ __forceinline__ float2 h2f(unsigned v) {
    __half2 h = *reinterpret_cast<__half2*>(&v);
    return __half22float2(h);
}

__global__ void __launch_bounds__(256) k_p(const int* __restrict__ bbox,
                                           float* __restrict__ out_p) {
    int gw = blockIdx.x * 8 + (threadIdx.x >> 5);
    if (gw >= BB * LL * KNN) return;
    int lane = threadIdx.x & 31;

    int m1 = 0, m2 = 0, m3 = 0, m4 = 0;
    if (lane == 0) {
        int bl = gw / KNN;
        int b = bl >> 10;
        int j = g_topk[gw];
        int4 bi = ((const int4*)bbox)[bl];
        int4 bj = ((const int4*)bbox)[b * LL + j];
        m1 = midx(bi.x - bj.x);          // ex1
        m2 = midx(bi.z - bj.z);          // ex2
        m3 = midx(bi.y - bj.y);          // ey1
        m4 = midx(bi.w - bj.w);          // ey2
    }
    m1 = __shfl_sync(0xffffffffu, m1, 0);
    m2 = __shfl_sync(0xffffffffu, m2, 0);
    m3 = __shfl_sync(0xffffffffu, m3, 0);
    m4 = __shfl_sync(0xffffffffu, m4, 0);

    const __half* Tp = (const __half*)g_Th;
    const __half* t0 = Tp + (size_t)(0 * TABN + m1) * HID;
    const __half* t1 = Tp + (size_t)(1 * TABN + m2) * HID;
    const __half* t2 = Tp + (size_t)(2 * TABN + m3) * HID;
    const __half* t3 = Tp + (size_t)(3 * TABN + m4) * HID;
    float* dst = out_p + (size_t)gw * HID;

#pragma unroll
    for (int seg = 0; seg < 6; seg++) {
        int o = seg * 128 + lane * 4;
        uint2 a  = *(const uint2*)(t0 + o);
        uint2 bq = *(const uint2*)(t1 + o);
        uint2 d  = *(const uint2*)(t2 + o);
        uint2 e  = *(const uint2*)(t3 + o);

        float2 s0, s1, ta, tb;
        ta = h2f(a.x); tb = h2f(bq.x); s0.x = ta.x + tb.x; s0.y = ta.y + tb.y;
        ta = h2f(d.x); tb = h2f(e.x);  s0.x += ta.x + tb.x; s0.y += ta.y + tb.y;
        ta = h2f(a.y); tb = h2f(bq.y); s1.x = ta.x + tb.x; s1.y = ta.y + tb.y;
        ta = h2f(d.y); tb = h2f(e.y);  s1.x += ta.x + tb.x; s1.y += ta.y + tb.y;

        __stcs((float4*)&dst[o], make_float4(s0.x, s0.y, s1.x, s1.y));
    }
}

// ---------------------------------------------------------------------------
extern "C" void kernel_launch(void* const* d_in, const int* in_sizes, int n_in,
                              void* d_out, int out_size) {
    const int*   bbox  = (const int*)d_in[0];
    const int*   amask = (const int*)d_in[1];
    const float* x_tab = (const float*)d_in[2];
    const float* y_tab = (const float*)d_in[3];
    const float* h_tab = (const float*)d_in[4];
    const float* w_tab = (const float*)d_in[5];
    const float* Wtl   = (const float*)d_in[6];
    const float* btl   = (const float*)d_in[7];
    const float* Wtr   = (const float*)d_in[8];
    const float* btr   = (const float*)d_in[9];
    const float* Wbl   = (const float*)d_in[10];
    const float* bbl   = (const float*)d_in[11];
    const float* Wbr   = (const float*)d_in[12];
    const float* bbr   = (const float*)d_in[13];
    const float* ln_g  = (const float*)d_in[14];
    const float* ln_b  = (const float*)d_in[15];
    (void)in_sizes; (void)n_in; (void)out_size;

    float* out = (float*)d_out;

    static cudaStream_t sA = nullptr, sB = nullptr;
    static cudaEvent_t eF = nullptr, eA = nullptr, eB = nullptr, eM = nullptr;
    static bool attrSet = false;
    if (!attrSet) {
        cudaFuncSetAttribute(k_tables,
                             cudaFuncAttributeMaxDynamicSharedMemorySize, SMEM_TB);
        attrSet = true;
    }
    if (!sA) {
        cudaStreamCaptureStatus st = cudaStreamCaptureStatusNone;
        cudaStreamIsCapturing((cudaStream_t)0, &st);
        if (st == cudaStreamCaptureStatusNone) {
            cudaStreamCreateWithFlags(&sA, cudaStreamNonBlocking);
            cudaStreamCreateWithFlags(&sB, cudaStreamNonBlocking);
            cudaEventCreateWithFlags(&eF, cudaEventDisableTiming);
            cudaEventCreateWithFlags(&eA, cudaEventDisableTiming);
            cudaEventCreateWithFlags(&eB, cudaEventDisableTiming);
            cudaEventCreateWithFlags(&eM, cudaEventDisableTiming);
        }
    }

    if (sA) {
        cudaEventRecord(eF, 0);
        cudaStreamWaitEvent(sA, eF, 0);
        cudaStreamWaitEvent(sB, eF, 0);
        // branch A: sin -> tables (tensor-core HMMA)
        k_sin<<<(TABN * HPE + 255) / 256, 256, 0, sA>>>();
        k_tables<<<dim3(HID / 64, TABN / 128, 4), 256, SMEM_TB, sA>>>(
            Wtl, Wtr, Wbl, Wbr, btl, btr, bbl, bbr);
        // branch B: centers -> knn select (gates k_p), then mask off-path
        k_centers<<<(BB * LL + 255) / 256, 256, 0, sB>>>(bbox, amask);
        k_knn<<<BB * LL, 512, 0, sB>>>(out + OFF_TOPK);
        cudaEventRecord(eB, sB);                            // gate for k_p
        k_mask<<<BB * LL, 256, 0, sB>>>(out + OFF_MASK);    // overlaps k_p
        cudaEventRecord(eM, sB);                            // join for capture
        // main stream: layout (independent)
        k_layout<<<BB * LL, 256>>>(bbox, x_tab, y_tab, h_tab, w_tab, ln_g, ln_b, out);
        // join: k_p depends on tables + knn-select only
        cudaEventRecord(eA, sA);
        cudaStreamWaitEvent(0, eA, 0);
        cudaStreamWaitEvent(0, eB, 0);
        k_p<<<(BB * LL * KNN + 7) / 8, 256>>>(bbox, out + OFF_P);
        // close the fork: join k_mask's tail into the capture stream
        cudaStreamWaitEvent(0, eM, 0);
    } else {
        k_sin<<<(TABN * HPE + 255) / 256, 256>>>();
        k_centers<<<(BB * LL + 255) / 256, 256>>>(bbox, amask);
        k_tables<<<dim3(HID / 64, TABN / 128, 4), 256, SMEM_TB>>>(
            Wtl, Wtr, Wbl, Wbr, btl, btr, bbl, bbr);
        k_layout<<<BB * LL, 256>>>(bbox, x_tab, y_tab, h_tab, w_tab, ln_g, ln_b, out);
        k_knn<<<BB * LL, 512>>>(out + OFF_TOPK);
        k_mask<<<BB * LL, 256>>>(out + OFF_MASK);
        k_p<<<(BB * LL * KNN + 7) / 8, 256>>>(bbox, out + OFF_P);
    }
}

// round 16
// speedup vs baseline: 1.0813x; 1.0813x over previous
#include <cuda_runtime.h>
#include <cuda_fp16.h>
#include <math.h>

// Problem constants (fixed by setup_inputs)
#define BB   2
#define LL   1024
#define KNN  50
#define HID  768
#define PE   384
#define HPE  192
#define TABN 1024

#define N_LAYOUT (BB*LL*HID)
#define N_P      (BB*LL*KNN*HID)
#define N_TOPK   (BB*LL*KNN)
#define OFF_P    (N_LAYOUT)
#define OFF_TOPK (N_LAYOUT + N_P)
#define OFF_MASK (OFF_TOPK + N_TOPK)

#define BP   196                         // B smem word pitch (half2 units)
#define SMEM_TB (64 * BP * 4 + 64 * 4)   // B tile + bias = 50432 B

typedef unsigned long long ull;

// Scratch (no dynamic allocation allowed)
__device__ __half g_sinh[TABN * PE];          // 0.75 MB sinusoidal table (fp16)
__device__ uint4  g_Th[4 * TABN * HID / 8];   // 6.3 MB fused lookup tables (fp16)
__device__ int    g_topk[BB * LL * KNN];      // topk indices for k_p / k_mask
__device__ float  g_cx[BB * LL], g_cy[BB * LL];

// ---------------------------------------------------------------------------
// Kernel 1: sinusoidal table (numpy f32 rounding of freq/angle), fp16 out
// ---------------------------------------------------------------------------
__global__ void k_sin() {
    int idx = blockIdx.x * blockDim.x + threadIdx.x;
    if (idx >= TABN * HPE) return;
    int m = idx / HPE;
    int j = idx - m * HPE;
    if (m == 0) {
        g_sinh[j] = __float2half(0.f);
        g_sinh[HPE + j] = __float2half(0.f);
        return;
    }
    const float c = (float)(-9.210340371976184 / 191.0);   // -ln(10000)/(half-1)
    float freq = expf((float)j * c);
    float ang  = (float)m * freq;                           // exact f32 angle
    g_sinh[m * PE + j]       = __float2half(sinf(ang));
    g_sinh[m * PE + HPE + j] = __float2half(cosf(ang));
}

// ---------------------------------------------------------------------------
// Kernel 2: fused tables T_t = sin_tab @ A_t^T via HMMA (mma.sync m16n8k16,
// fp16 in, f32 accum). Block = 128(M) x 64(N) tile, 8 warps, 24 K-steps.
// ---------------------------------------------------------------------------
__device__ __forceinline__ void mma16816(float* d,
        unsigned a0, unsigned a1, unsigned a2, unsigned a3,
        unsigned b0, unsigned b1) {
    asm volatile(
        "mma.sync.aligned.m16n8k16.row.col.f32.f16.f16.f32 "
        "{%0,%1,%2,%3}, {%4,%5,%6,%7}, {%8,%9}, {%0,%1,%2,%3};"
        : "+f"(d[0]), "+f"(d[1]), "+f"(d[2]), "+f"(d[3])
        : "r"(a0), "r"(a1), "r"(a2), "r"(a3), "r"(b0), "r"(b1));
}

__global__ void __launch_bounds__(256) k_tables(
        const float* __restrict__ Wtl, const float* __restrict__ Wtr,
        const float* __restrict__ Wbl, const float* __restrict__ Wbr,
        const float* __restrict__ btl, const float* __restrict__ btr,
        const float* __restrict__ bbl, const float* __restrict__ bbr) {
    int t = blockIdx.z;
    const float *WA, *WBp; int off;
    if      (t == 0) { WA = Wtl; WBp = Wbl; off = 0;  }
    else if (t == 1) { WA = Wtr; WBp = Wbr; off = 0;  }
    else if (t == 2) { WA = Wtl; WBp = Wtr; off = PE; }
    else             { WA = Wbl; WBp = Wbr; off = PE; }

    extern __shared__ unsigned sh[];
    unsigned* Bs = sh;                         // [64][BP] half2 words
    float* bias = (float*)(sh + 64 * BP);      // [64]

    int n0 = blockIdx.x * 64;
    int m0 = blockIdx.y * 128;

    for (int idx = threadIdx.x; idx < 64 * 192; idx += 256) {
        int r = idx / 192, wc = idx - r * 192;
        const float* wp = WA + (size_t)(n0 + r) * HID + off + wc * 2;
        const float* vp = WBp + (size_t)(n0 + r) * HID + off + wc * 2;
        float2 w = *(const float2*)wp;
        float2 v = *(const float2*)vp;
        __half2 h = __floats2half2_rn(w.x + v.x, w.y + v.y);
        Bs[r * BP + wc] = *(unsigned*)&h;
    }
    if (t == 0 && threadIdx.x < 64) {
        int o = n0 + threadIdx.x;
        bias[threadIdx.x] = btl[o] + btr[o] + bbl[o] + bbr[o];
    }
    __syncthreads();

    int w = threadIdx.x >> 5;
    int lane = threadIdx.x & 31;
    int g = lane >> 2;
    int q = lane & 3;
    int mrow = m0 + w * 16 + g;

    float d[8][4];
#pragma unroll
    for (int nt = 0; nt < 8; nt++)
#pragma unroll
        for (int i = 0; i < 4; i++) d[nt][i] = 0.f;

    const __half* A = g_sinh;
    for (int k0 = 0; k0 < PE; k0 += 16) {
        unsigned a0 = *(const unsigned*)&A[(size_t)mrow * PE + k0 + 2 * q];
        unsigned a1 = *(const unsigned*)&A[(size_t)(mrow + 8) * PE + k0 + 2 * q];
        unsigned a2 = *(const unsigned*)&A[(size_t)mrow * PE + k0 + 2 * q + 8];
        unsigned a3 = *(const unsigned*)&A[(size_t)(mrow + 8) * PE + k0 + 2 * q + 8];
        int kw = (k0 >> 1) + q;
#pragma unroll
        for (int nt = 0; nt < 8; nt++) {
            unsigned b0 = Bs[(nt * 8 + g) * BP + kw];
            unsigned b1 = Bs[(nt * 8 + g) * BP + kw + 4];
            mma16816(d[nt], a0, a1, a2, a3, b0, b1);
        }
    }

    __half* Tp = (__half*)g_Th;
#pragma unroll
    for (int nt = 0; nt < 8; nt++) {
        int c = nt * 8 + 2 * q;
        float b0v = 0.f, b1v = 0.f;
        if (t == 0) { b0v = bias[c]; b1v = bias[c + 1]; }
        __half2 h0 = __floats2half2_rn(d[nt][0] + b0v, d[nt][1] + b1v);
        __half2 h1 = __floats2half2_rn(d[nt][2] + b0v, d[nt][3] + b1v);
        size_t base = ((size_t)(t * TABN) + mrow) * HID + n0 + c;
        *(unsigned*)&Tp[base] = *(unsigned*)&h0;
        *(unsigned*)&Tp[base + (size_t)8 * HID] = *(unsigned*)&h1;
    }
}

// ---------------------------------------------------------------------------
// Kernel 3: layout_emb gathers + LayerNorm
// ---------------------------------------------------------------------------
__device__ __forceinline__ float block_sum_256(float v, volatile float* red) {
#pragma unroll
    for (int o = 16; o > 0; o >>= 1) v += __shfl_down_sync(0xffffffffu, v, o);
    if ((threadIdx.x & 31) == 0) red[threadIdx.x >> 5] = v;
    __syncthreads();
    if (threadIdx.x < 32) {
        float t = (threadIdx.x < 8) ? red[threadIdx.x] : 0.f;
#pragma unroll
        for (int o = 16; o > 0; o >>= 1) t += __shfl_down_sync(0xffffffffu, t, o);
        if (threadIdx.x == 0) red[8] = t;
    }
    __syncthreads();
    return red[8];
}

__global__ void k_layout(const int* __restrict__ bbox,
                         const float* __restrict__ xt, const float* __restrict__ yt,
                         const float* __restrict__ ht, const float* __restrict__ wt,
                         const float* __restrict__ g,  const float* __restrict__ be,
                         float* __restrict__ out) {
    int row = blockIdx.x;
    int4 bb = ((const int4*)bbox)[row];
    int t = threadIdx.x;

    float v[3]; int cs[3];
#pragma unroll
    for (int s = 0; s < 3; s++) {
        int c = t + s * 256; cs[s] = c;
        int seg = c >> 7, o = c & 127;
        const float* tab; int idx;
        switch (seg) {
            case 0: tab = xt; idx = bb.x; break;
            case 1: tab = yt; idx = bb.y; break;
            case 2: tab = xt; idx = bb.z; break;
            case 3: tab = yt; idx = bb.w; break;
            case 4: tab = ht; idx = bb.w - bb.y; break;
            default: tab = wt; idx = bb.z - bb.x; break;
        }
        v[s] = tab[idx * 128 + o];
    }

    __shared__ float red[9];
    float mu = block_sum_256(v[0] + v[1] + v[2], red) * (1.f / 768.f);
    float d0 = v[0] - mu, d1 = v[1] - mu, d2 = v[2] - mu;
    float var = block_sum_256(d0 * d0 + d1 * d1 + d2 * d2, red) * (1.f / 768.f);
    float inv = rsqrtf(var + 1e-12f);

    float* dst = out + (size_t)row * HID;
    dst[cs[0]] = d0 * inv * g[cs[0]] + be[cs[0]];
    dst[cs[1]] = d1 * inv * g[cs[1]] + be[cs[1]];
    dst[cs[2]] = d2 * inv * g[cs[2]] + be[cs[2]];
}

// ---------------------------------------------------------------------------
// Kernel 3b: box centers (masked -> huge coordinate)
// ---------------------------------------------------------------------------
__global__ void k_centers(const int* __restrict__ bbox, const int* __restrict__ amask) {
    int j = blockIdx.x * 256 + threadIdx.x;
    if (j >= BB * LL) return;
    int4 bv = ((const int4*)bbox)[j];
    float x1, y1, x2, y2;
    if (amask[j] == 0) { x1 = y1 = x2 = y2 = 1.0e8f; }
    else { x1 = (float)bv.x; y1 = (float)bv.y; x2 = (float)bv.z; y2 = (float)bv.w; }
    g_cx[j] = __fmul_rn(__fadd_rn(x1, x2), 0.5f);
    g_cy[j] = __fmul_rn(__fadd_rn(y1, y2), 0.5f);
}

// ---------------------------------------------------------------------------
// Kernel 4: KNN top-50 SELECT ONLY — 256 threads (proven fastest config).
// Writes g_topk + topk float output; mask built off-path by k_mask.
// ---------------------------------------------------------------------------
__global__ void __launch_bounds__(256) k_knn(float* __restrict__ out_topk) {
    __shared__ unsigned u[LL];
    __shared__ ull cand[LL];
    __shared__ int hist[256];
    __shared__ int s_bin, s_wt, s_cnt;

    int row = blockIdx.x;
    int b = row >> 10;
    int tid = threadIdx.x;

    float cx = g_cx[row], cy = g_cy[row];
    const float* bx = g_cx + b * LL;
    const float* by = g_cy + b * LL;
    for (int j = tid; j < LL; j += 256) {
        float dx = __fadd_rn(cx, -bx[j]);
        float dy = __fadd_rn(cy, -by[j]);
        float d  = __fadd_rn(__fmul_rn(dx, dx), __fmul_rn(dy, dy));
        u[j] = __float_as_uint(d);
    }
    __syncthreads();

    unsigned prefix = 0;
    int want = KNN;
    for (int pass = 0; pass < 4; pass++) {
        int shift = 24 - 8 * pass;
        hist[tid] = 0;
        __syncthreads();
        for (int j = tid; j < LL; j += 256) {
            unsigned key = u[j];
            bool ok = (pass == 0) || ((key >> (shift + 8)) == prefix);
            if (ok) atomicAdd(&hist[(key >> shift) & 255], 1);
        }
        __syncthreads();
        if (tid < 32) {
            int h[8], s = 0;
#pragma unroll
            for (int k = 0; k < 8; k++) { h[k] = hist[tid * 8 + k]; s += h[k]; }
            int inc = s;
#pragma unroll
            for (int o = 1; o < 32; o <<= 1) {
                int v = __shfl_up_sync(0xffffffffu, inc, o);
                if (tid >= o) inc += v;
            }
            int c = inc - s;
#pragma unroll
            for (int k = 0; k < 8; k++) {
                if (want > c && want <= c + h[k]) { s_bin = tid * 8 + k; s_wt = want - c; }
                c += h[k];
            }
        }
        __syncthreads();
        prefix = (prefix << 8) | (unsigned)s_bin;
        want = s_wt;
        __syncthreads();
    }
    unsigned T = prefix;

    if (tid == 0) s_cnt = 0;
    __syncthreads();
    for (int j = tid; j < LL; j += 256) {
        if (u[j] <= T) {
            int p = atomicAdd(&s_cnt, 1);
            cand[p] = ((ull)u[j] << 32) | (unsigned)j;
        }
    }
    __syncthreads();
    int cnt = s_cnt;
    int n = 64; while (n < cnt) n <<= 1;
    for (int j = cnt + tid; j < n; j += 256) cand[j] = ~0ULL;

    for (unsigned k2 = 2; k2 <= (unsigned)n; k2 <<= 1) {
        for (unsigned jj = k2 >> 1; jj > 0; jj >>= 1) {
            __syncthreads();
            for (unsigned idx = tid; idx < (unsigned)n; idx += 256) {
                unsigned ixj = idx ^ jj;
                if (ixj > idx) {
                    ull a = cand[idx], c2 = cand[ixj];
                    bool asc = ((idx & k2) == 0);
                    if ((a > c2) == asc) { cand[idx] = c2; cand[ixj] = a; }
                }
            }
        }
    }
    __syncthreads();

    if (tid < KNN) {
        int idxk = (int)(cand[tid] & 0xffffffffu);
        g_topk[row * KNN + tid] = idxk;
        out_topk[row * KNN + tid] = (float)idxk;
    }
}

// ---------------------------------------------------------------------------
// Kernel 4b: local_mask from g_topk (off the k_p critical path)
// ---------------------------------------------------------------------------
__global__ void __launch_bounds__(256) k_mask(float* __restrict__ out_mask) {
    __shared__ unsigned char flg[LL];
    int row = blockIdx.x;
    int tid = threadIdx.x;
    for (int j = tid; j < LL; j += 256) flg[j] = 0;
    __syncthreads();
    if (tid < KNN) flg[g_topk[row * KNN + tid]] = 1;
    __syncthreads();
    float* mrow = out_mask + (size_t)row * LL;
    for (int j = tid; j < LL; j += 256) __stcs(&mrow[j], (float)flg[j]);
}

// ---------------------------------------------------------------------------
// Kernel 5: p = T0[m1] + T1[m2] + T2[m3] + T3[m4]  (fp16 tables, f32 out)
// R12/R13 winner: lane0+shfl indices; uint2 loads, coalesced float4 stores.
// ---------------------------------------------------------------------------
__device__ __forceinline__ int midx(int d) {
    d = d < -1000 ? -1000 : (d > 1000 ? 1000 : d);
    return d & 1023;
}
__device__ __forceinline__ float2 h2f(unsigned v) {
    __half2 h = *reinterpret_cast<__half2*>(&v);
    return __half22float2(h);
}

__global__ void __launch_bounds__(256) k_p(const int* __restrict__ bbox,
                                           float* __restrict__ out_p) {
    int gw = blockIdx.x * 8 + (threadIdx.x >> 5);
    if (gw >= BB * LL * KNN) return;
    int lane = threadIdx.x & 31;

    int m1 = 0, m2 = 0, m3 = 0, m4 = 0;
    if (lane == 0) {
        int bl = gw / KNN;
        int b = bl >> 10;
        int j = g_topk[gw];
        int4 bi = ((const int4*)bbox)[bl];
        int4 bj = ((const int4*)bbox)[b * LL + j];
        m1 = midx(bi.x - bj.x);          // ex1
        m2 = midx(bi.z - bj.z);          // ex2
        m3 = midx(bi.y - bj.y);          // ey1
        m4 = midx(bi.w - bj.w);          // ey2
    }
    m1 = __shfl_sync(0xffffffffu, m1, 0);
    m2 = __shfl_sync(0xffffffffu, m2, 0);
    m3 = __shfl_sync(0xffffffffu, m3, 0);
    m4 = __shfl_sync(0xffffffffu, m4, 0);

    const __half* Tp = (const __half*)g_Th;
    const __half* t0 = Tp + (size_t)(0 * TABN + m1) * HID;
    const __half* t1 = Tp + (size_t)(1 * TABN + m2) * HID;
    const __half* t2 = Tp + (size_t)(2 * TABN + m3) * HID;
    const __half* t3 = Tp + (size_t)(3 * TABN + m4) * HID;
    float* dst = out_p + (size_t)gw * HID;

#pragma unroll
    for (int seg = 0; seg < 6; seg++) {
        int o = seg * 128 + lane * 4;
        uint2 a  = *(const uint2*)(t0 + o);
        uint2 bq = *(const uint2*)(t1 + o);
        uint2 d  = *(const uint2*)(t2 + o);
        uint2 e  = *(const uint2*)(t3 + o);

        float2 s0, s1, ta, tb;
        ta = h2f(a.x); tb = h2f(bq.x); s0.x = ta.x + tb.x; s0.y = ta.y + tb.y;
        ta = h2f(d.x); tb = h2f(e.x);  s0.x += ta.x + tb.x; s0.y += ta.y + tb.y;
        ta = h2f(a.y); tb = h2f(bq.y); s1.x = ta.x + tb.x; s1.y = ta.y + tb.y;
        ta = h2f(d.y); tb = h2f(e.y);  s1.x += ta.x + tb.x; s1.y += ta.y + tb.y;

        __stcs((float4*)&dst[o], make_float4(s0.x, s0.y, s1.x, s1.y));
    }
}

// ---------------------------------------------------------------------------
extern "C" void kernel_launch(void* const* d_in, const int* in_sizes, int n_in,
                              void* d_out, int out_size) {
    const int*   bbox  = (const int*)d_in[0];
    const int*   amask = (const int*)d_in[1];
    const float* x_tab = (const float*)d_in[2];
    const float* y_tab = (const float*)d_in[3];
    const float* h_tab = (const float*)d_in[4];
    const float* w_tab = (const float*)d_in[5];
    const float* Wtl   = (const float*)d_in[6];
    const float* btl   = (const float*)d_in[7];
    const float* Wtr   = (const float*)d_in[8];
    const float* btr   = (const float*)d_in[9];
    const float* Wbl   = (const float*)d_in[10];
    const float* bbl   = (const float*)d_in[11];
    const float* Wbr   = (const float*)d_in[12];
    const float* bbr   = (const float*)d_in[13];
    const float* ln_g  = (const float*)d_in[14];
    const float* ln_b  = (const float*)d_in[15];
    (void)in_sizes; (void)n_in; (void)out_size;

    float* out = (float*)d_out;

    static cudaStream_t sA = nullptr, sB = nullptr;
    static cudaEvent_t eF = nullptr, eA = nullptr, eB = nullptr, eM = nullptr;
    static bool attrSet = false;
    if (!attrSet) {
        cudaFuncSetAttribute(k_tables,
                             cudaFuncAttributeMaxDynamicSharedMemorySize, SMEM_TB);
        attrSet = true;
    }
    if (!sA) {
        cudaStreamCaptureStatus st = cudaStreamCaptureStatusNone;
        cudaStreamIsCapturing((cudaStream_t)0, &st);
        if (st == cudaStreamCaptureStatusNone) {
            cudaStreamCreateWithFlags(&sA, cudaStreamNonBlocking);
            cudaStreamCreateWithFlags(&sB, cudaStreamNonBlocking);
            cudaEventCreateWithFlags(&eF, cudaEventDisableTiming);
            cudaEventCreateWithFlags(&eA, cudaEventDisableTiming);
            cudaEventCreateWithFlags(&eB, cudaEventDisableTiming);
            cudaEventCreateWithFlags(&eM, cudaEventDisableTiming);
        }
    }

    if (sA) {
        cudaEventRecord(eF, 0);
        cudaStreamWaitEvent(sA, eF, 0);
        cudaStreamWaitEvent(sB, eF, 0);
        // branch A: sin -> tables (tensor-core HMMA)
        k_sin<<<(TABN * HPE + 255) / 256, 256, 0, sA>>>();
        k_tables<<<dim3(HID / 64, TABN / 128, 4), 256, SMEM_TB, sA>>>(
            Wtl, Wtr, Wbl, Wbr, btl, btr, bbl, bbr);
        // branch B: centers -> knn select (gates k_p), then mask off-path
        k_centers<<<(BB * LL + 255) / 256, 256, 0, sB>>>(bbox, amask);
        k_knn<<<BB * LL, 256, 0, sB>>>(out + OFF_TOPK);
        cudaEventRecord(eB, sB);                            // gate for k_p
        k_mask<<<BB * LL, 256, 0, sB>>>(out + OFF_MASK);    // overlaps k_p
        cudaEventRecord(eM, sB);                            // join for capture
        // main stream: layout (independent)
        k_layout<<<BB * LL, 256>>>(bbox, x_tab, y_tab, h_tab, w_tab, ln_g, ln_b, out);
        // join: k_p depends on tables + knn-select only
        cudaEventRecord(eA, sA);
        cudaStreamWaitEvent(0, eA, 0);
        cudaStreamWaitEvent(0, eB, 0);
        k_p<<<(BB * LL * KNN + 7) / 8, 256>>>(bbox, out + OFF_P);
        // close the fork: join k_mask's tail into the capture stream
        cudaStreamWaitEvent(0, eM, 0);
    } else {
        k_sin<<<(TABN * HPE + 255) / 256, 256>>>();
        k_centers<<<(BB * LL + 255) / 256, 256>>>(bbox, amask);
        k_tables<<<dim3(HID / 64, TABN / 128, 4), 256, SMEM_TB>>>(
            Wtl, Wtr, Wbl, Wbr, btl, btr, bbl, bbr);
        k_layout<<<BB * LL, 256>>>(bbox, x_tab, y_tab, h_tab, w_tab, ln_g, ln_b, out);
        k_knn<<<BB * LL, 256>>>(out + OFF_TOPK);
        k_mask<<<BB * LL, 256>>>(out + OFF_MASK);
        k_p<<<(BB * LL * KNN + 7) / 8, 256>>>(bbox, out + OFF_P);
    }
}